// round 2
// baseline (speedup 1.0000x reference)
#include <cuda_runtime.h>
#include <cstdint>

// ---------------------------------------------------------------------------
// Upsampling_77214922047593
//   latent = support[b, idx]             (row gather)
//   h1 = unary(latent @ W1)              -> unary commutes with row gather!
//   h2 = unary(h1 @ W2)
//   out = unary((gather(h2) + query) @ W3)
// So layers 1&2 run on the 65536 support rows, layer 3 on 262144 query rows.
// GEMMs via 3xTF32 mma.sync.m16n8k8 (hi*hi + lo*hi + hi*lo), fused
// GroupNorm(32 groups of 8) + affine + leaky-relu epilogue in registers
// (group == one n8 MMA tile; quad shfl reduction).
// ---------------------------------------------------------------------------

namespace {
constexpr int Bc   = 4;
constexpr int Nn   = 65536;
constexpr int Mm   = 16384;
constexpr int CIN  = 512;
constexpr int COUT = 256;
constexpr float EPSv   = 1e-5f;
constexpr float SLOPEv = 0.1f;

constexpr int ROWS12 = Bc * Mm;   // 65536 rows for layers 1 & 2
constexpr int ROWS3  = Bc * Nn;   // 262144 rows for layer 3

constexpr int TILE_M = 128;       // rows per block
constexpr int KC     = 32;        // K-chunk
constexpr int ASTR   = 36;        // A smem stride (floats) - conflict free
constexpr int BSTR   = 264;       // B smem stride (floats) - conflict free

constexpr int SMEM_FLOATS = 2 * TILE_M * ASTR + 2 * KC * BSTR; // 9216 + 16896
constexpr size_t SMEM_BYTES = (size_t)SMEM_FLOATS * sizeof(float)
                            + TILE_M * sizeof(int);            // gather rows
} // namespace

// scratch (allocation-free rule: __device__ globals)
__device__ float g_h1[(size_t)ROWS12 * COUT];
__device__ float g_h2[(size_t)ROWS12 * COUT];

__device__ __forceinline__ uint32_t f2tf(float x) {
    uint32_t r;
    asm("cvt.rna.tf32.f32 %0, %1;" : "=r"(r) : "f"(x));
    return r;
}

#define MMA_TF32(c, a, b)                                                  \
    asm("mma.sync.aligned.m16n8k8.row.col.f32.tf32.tf32.f32 "              \
        "{%0,%1,%2,%3}, {%4,%5,%6,%7}, {%8,%9}, {%0,%1,%2,%3};\n"          \
        : "+f"((c)[0]), "+f"((c)[1]), "+f"((c)[2]), "+f"((c)[3])           \
        : "r"((a)[0]), "r"((a)[1]), "r"((a)[2]), "r"((a)[3]),              \
          "r"((b)[0]), "r"((b)[1]))

// MODE 0: A = support (K=512) -> g_h1
// MODE 1: A = g_h1    (K=256) -> g_h2
// MODE 2: A = query + gather(g_h2) (K=256) -> out
template <int MODE>
__global__ void __launch_bounds__(256, 1)
fused_gemm_gn(const float* __restrict__ Aext,
              const float* __restrict__ W,
              const float* __restrict__ bias,
              const float* __restrict__ gamma,
              const float* __restrict__ beta,
              const int*   __restrict__ idx,
              float*       __restrict__ Oext)
{
    constexpr int K = (MODE == 0) ? CIN : COUT;

    extern __shared__ float sm[];
    float* a_hi = sm;
    float* a_lo = a_hi + TILE_M * ASTR;
    float* b_hi = a_lo + TILE_M * ASTR;
    float* b_lo = b_hi + KC * BSTR;
    int*   s_grow = (int*)(b_lo + KC * BSTR);

    const int tid  = threadIdx.x;
    const int lane = tid & 31;
    const int warp = tid >> 5;
    const int rowBlk = blockIdx.x * TILE_M;
    const int wr = (warp >> 2) * 64;   // warp row offset in tile
    const int wc = (warp & 3) * 64;    // warp col offset in tile

    const float* Asrc = (MODE == 1) ? g_h1 : Aext;
    float*       Odst = (MODE == 0) ? g_h1 : ((MODE == 1) ? g_h2 : Oext);

    if (MODE == 2) {
        if (tid < TILE_M) {
            int grow = rowBlk + tid;
            int b    = grow >> 16;               // / Nn
            s_grow[tid] = b * Mm + idx[grow];
        }
    }

    float acc[4][8][4];
#pragma unroll
    for (int mi = 0; mi < 4; mi++)
#pragma unroll
        for (int j = 0; j < 8; j++)
#pragma unroll
            for (int c = 0; c < 4; c++) acc[mi][j][c] = 0.f;

#pragma unroll 1
    for (int kc = 0; kc < K; kc += KC) {
        __syncthreads();

        // ---- stage W chunk [KC][256] -> b_hi/b_lo (tf32 split) ----
#pragma unroll
        for (int i = 0; i < 8; i++) {
            int s = tid + i * 256;
            int k = s >> 6;
            int c = (s & 63) * 4;
            float4 w = *reinterpret_cast<const float4*>(
                W + (size_t)(kc + k) * COUT + c);
            float4 h, l;
            h.x = __uint_as_float(f2tf(w.x)); l.x = __uint_as_float(f2tf(w.x - h.x));
            h.y = __uint_as_float(f2tf(w.y)); l.y = __uint_as_float(f2tf(w.y - h.y));
            h.z = __uint_as_float(f2tf(w.z)); l.z = __uint_as_float(f2tf(w.z - h.z));
            h.w = __uint_as_float(f2tf(w.w)); l.w = __uint_as_float(f2tf(w.w - h.w));
            *reinterpret_cast<float4*>(b_hi + k * BSTR + c) = h;
            *reinterpret_cast<float4*>(b_lo + k * BSTR + c) = l;
        }

        // ---- stage A chunk [128][KC] -> a_hi/a_lo (tf32 split) ----
#pragma unroll
        for (int i = 0; i < 4; i++) {
            int s = tid + i * 256;
            int r = s >> 3;
            int c = (s & 7) * 4;
            float4 v;
            if (MODE == 2) {
                float4 q = *reinterpret_cast<const float4*>(
                    Aext + (size_t)(rowBlk + r) * COUT + kc + c);
                float4 g = *reinterpret_cast<const float4*>(
                    g_h2 + (size_t)s_grow[r] * COUT + kc + c);
                v.x = q.x + g.x; v.y = q.y + g.y;
                v.z = q.z + g.z; v.w = q.w + g.w;
            } else {
                v = *reinterpret_cast<const float4*>(
                    Asrc + (size_t)(rowBlk + r) * K + kc + c);
            }
            float4 h, l;
            h.x = __uint_as_float(f2tf(v.x)); l.x = __uint_as_float(f2tf(v.x - h.x));
            h.y = __uint_as_float(f2tf(v.y)); l.y = __uint_as_float(f2tf(v.y - h.y));
            h.z = __uint_as_float(f2tf(v.z)); l.z = __uint_as_float(f2tf(v.z - h.z));
            h.w = __uint_as_float(f2tf(v.w)); l.w = __uint_as_float(f2tf(v.w - h.w));
            *reinterpret_cast<float4*>(a_hi + r * ASTR + c) = h;
            *reinterpret_cast<float4*>(a_lo + r * ASTR + c) = l;
        }
        __syncthreads();

        // ---- MMA over this chunk: 3xTF32 ----
#pragma unroll
        for (int k8 = 0; k8 < 4; k8++) {
            const int k0 = k8 * 8 + (lane & 3);
            uint32_t ah[4][4], al[4][4];
#pragma unroll
            for (int mi = 0; mi < 4; mi++) {
                const int r = wr + mi * 16 + (lane >> 2);
                const float* p = a_hi + r * ASTR + k0;
                ah[mi][0] = __float_as_uint(p[0]);
                ah[mi][1] = __float_as_uint(p[8 * ASTR]);
                ah[mi][2] = __float_as_uint(p[4]);
                ah[mi][3] = __float_as_uint(p[8 * ASTR + 4]);
                const float* q = a_lo + r * ASTR + k0;
                al[mi][0] = __float_as_uint(q[0]);
                al[mi][1] = __float_as_uint(q[8 * ASTR]);
                al[mi][2] = __float_as_uint(q[4]);
                al[mi][3] = __float_as_uint(q[8 * ASTR + 4]);
            }
            uint32_t bh[8][2], bl[8][2];
#pragma unroll
            for (int j = 0; j < 8; j++) {
                const int n = wc + j * 8 + (lane >> 2);
                bh[j][0] = __float_as_uint(b_hi[k0 * BSTR + n]);
                bh[j][1] = __float_as_uint(b_hi[(k0 + 4) * BSTR + n]);
                bl[j][0] = __float_as_uint(b_lo[k0 * BSTR + n]);
                bl[j][1] = __float_as_uint(b_lo[(k0 + 4) * BSTR + n]);
            }
#pragma unroll
            for (int mi = 0; mi < 4; mi++)
#pragma unroll
                for (int j = 0; j < 8; j++) {
                    MMA_TF32(acc[mi][j], ah[mi], bh[j]);
                    MMA_TF32(acc[mi][j], al[mi], bh[j]);
                    MMA_TF32(acc[mi][j], ah[mi], bl[j]);
                }
        }
    }

    // ---- fused epilogue: +bias, GroupNorm(group=8 ch = one n8 tile),
    //      gamma/beta, leaky relu, store ----
    const int qlane = lane & 3;
#pragma unroll
    for (int j = 0; j < 8; j++) {
        const int col = wc + j * 8 + 2 * qlane;
        const float2 bb = *reinterpret_cast<const float2*>(bias + col);
        const float2 gg = *reinterpret_cast<const float2*>(gamma + col);
        const float2 be = *reinterpret_cast<const float2*>(beta + col);
#pragma unroll
        for (int mi = 0; mi < 4; mi++) {
            float v0 = acc[mi][j][0] + bb.x;
            float v1 = acc[mi][j][1] + bb.y;
            float v2 = acc[mi][j][2] + bb.x;
            float v3 = acc[mi][j][3] + bb.y;

            float s0 = v0 + v1,           s1 = v2 + v3;
            float t0 = v0 * v0 + v1 * v1, t1 = v2 * v2 + v3 * v3;
            s0 += __shfl_xor_sync(0xffffffffu, s0, 1);
            s0 += __shfl_xor_sync(0xffffffffu, s0, 2);
            s1 += __shfl_xor_sync(0xffffffffu, s1, 1);
            s1 += __shfl_xor_sync(0xffffffffu, s1, 2);
            t0 += __shfl_xor_sync(0xffffffffu, t0, 1);
            t0 += __shfl_xor_sync(0xffffffffu, t0, 2);
            t1 += __shfl_xor_sync(0xffffffffu, t1, 1);
            t1 += __shfl_xor_sync(0xffffffffu, t1, 2);

            const float m0 = s0 * 0.125f, m1 = s1 * 0.125f;
            const float r0 = rsqrtf(fmaxf(t0 * 0.125f - m0 * m0, 0.f) + EPSv);
            const float r1 = rsqrtf(fmaxf(t1 * 0.125f - m1 * m1, 0.f) + EPSv);

            float y0 = (v0 - m0) * r0 * gg.x + be.x;
            float y1 = (v1 - m0) * r0 * gg.y + be.y;
            float y2 = (v2 - m1) * r1 * gg.x + be.x;
            float y3 = (v3 - m1) * r1 * gg.y + be.y;
            y0 = (y0 >= 0.f) ? y0 : SLOPEv * y0;
            y1 = (y1 >= 0.f) ? y1 : SLOPEv * y1;
            y2 = (y2 >= 0.f) ? y2 : SLOPEv * y2;
            y3 = (y3 >= 0.f) ? y3 : SLOPEv * y3;

            const size_t row = (size_t)rowBlk + wr + mi * 16 + (lane >> 2);
            *reinterpret_cast<float2*>(Odst + row * COUT + col) =
                make_float2(y0, y1);
            *reinterpret_cast<float2*>(Odst + (row + 8) * COUT + col) =
                make_float2(y2, y3);
        }
    }
}

extern "C" void kernel_launch(void* const* d_in, const int* in_sizes, int n_in,
                              void* d_out, int out_size)
{
    (void)in_sizes; (void)n_in; (void)out_size;
    const float* query   = (const float*)d_in[0];
    const float* support = (const float*)d_in[1];
    const int*   idx     = (const int*)d_in[2];
    const float* W1  = (const float*)d_in[3];
    const float* b1  = (const float*)d_in[4];
    const float* g1  = (const float*)d_in[5];
    const float* be1 = (const float*)d_in[6];
    const float* W2  = (const float*)d_in[7];
    const float* b2  = (const float*)d_in[8];
    const float* g2  = (const float*)d_in[9];
    const float* be2 = (const float*)d_in[10];
    const float* W3  = (const float*)d_in[11];
    const float* b3  = (const float*)d_in[12];
    const float* g3  = (const float*)d_in[13];
    const float* be3 = (const float*)d_in[14];
    float* out = (float*)d_out;

    cudaFuncSetAttribute(fused_gemm_gn<0>,
        cudaFuncAttributeMaxDynamicSharedMemorySize, (int)SMEM_BYTES);
    cudaFuncSetAttribute(fused_gemm_gn<1>,
        cudaFuncAttributeMaxDynamicSharedMemorySize, (int)SMEM_BYTES);
    cudaFuncSetAttribute(fused_gemm_gn<2>,
        cudaFuncAttributeMaxDynamicSharedMemorySize, (int)SMEM_BYTES);

    fused_gemm_gn<0><<<ROWS12 / TILE_M, 256, SMEM_BYTES>>>(
        support, W1, b1, g1, be1, nullptr, nullptr);
    fused_gemm_gn<1><<<ROWS12 / TILE_M, 256, SMEM_BYTES>>>(
        nullptr, W2, b2, g2, be2, nullptr, nullptr);
    fused_gemm_gn<2><<<ROWS3 / TILE_M, 256, SMEM_BYTES>>>(
        query, W3, b3, g3, be3, idx, out);
}

// round 4
// speedup vs baseline: 2.0004x; 2.0004x over previous
#include <cuda_runtime.h>
#include <cuda_bf16.h>
#include <cstdint>

// ---------------------------------------------------------------------------
// Upsampling_77214922047593 — legacy mma.sync bf16x3 version (sm_103 base ISA).
//   latent = support[b, idx]  (row gather; unary commutes with row gather)
//   h1 = unary(support @ W1)            65536 rows, K=512
//   h2 = unary(h1 @ W2)                 65536 rows, K=256
//   out = unary((gather(h2)+query)@W3)  262144 rows, K=256
// fp32 emulated as bf16 hi/lo split, 3 MMA passes (hi*hi + lo*hi + hi*lo)
// on mma.sync.m16n8k16.bf16 with fp32 accumulate.  CTA tile 128x256,
// 512 threads (16 warps, warp tile 32x64), double-buffered smem,
// cp.async weight staging from pre-split/transposed bf16 weights,
// fused GroupNorm(32 groups of 8ch) + affine + leaky-relu epilogue.
// ---------------------------------------------------------------------------

namespace {
constexpr int Mm   = 16384;
constexpr int CIN  = 512;
constexpr int COUT = 256;
constexpr float EPSv   = 1e-5f;
constexpr float SLOPEv = 0.1f;

constexpr int ROWS12 = 65536;
constexpr int ROWS3  = 262144;

constexpr int TILE_M = 128;
constexpr int KC     = 32;         // K per smem chunk
constexpr int ASTRE  = 40;         // padded row stride in bf16 elems (80B)

constexpr int A_BYTES   = TILE_M * ASTRE * 2;   // 10240 (one half: hi or lo)
constexpr int B_BYTES   = COUT   * ASTRE * 2;   // 20480
constexpr int BUF_BYTES = 2 * A_BYTES + 2 * B_BYTES;  // 61440
constexpr size_t SMEM_DYN = 2 * (size_t)BUF_BYTES;    // 122880
} // namespace

__device__ float g_h1[(size_t)ROWS12 * COUT];
__device__ float g_h2[(size_t)ROWS12 * COUT];
// pre-split, pre-transposed weights: Wt[layer][n][k]
__device__ __nv_bfloat16 g_Wth[3][COUT][CIN];
__device__ __nv_bfloat16 g_Wtl[3][COUT][CIN];

// ---------------- helpers ----------------
__device__ __forceinline__ uint32_t smem_u32(const void* p) {
    uint32_t a;
    asm("{ .reg .u64 t; cvta.to.shared.u64 t, %1; cvt.u32.u64 %0, t; }"
        : "=r"(a) : "l"(p));
    return a;
}

#define LDSM4(r, addr)                                                         \
    asm volatile("ldmatrix.sync.aligned.m8n8.x4.shared.b16 {%0,%1,%2,%3}, [%4];" \
        : "=r"((r)[0]), "=r"((r)[1]), "=r"((r)[2]), "=r"((r)[3]) : "r"(addr))

#define MMA_BF16(c, a, b0, b1)                                                 \
    asm volatile("mma.sync.aligned.m16n8k16.row.col.f32.bf16.bf16.f32 "        \
        "{%0,%1,%2,%3}, {%4,%5,%6,%7}, {%8,%9}, {%0,%1,%2,%3};"                \
        : "+f"((c)[0]), "+f"((c)[1]), "+f"((c)[2]), "+f"((c)[3])               \
        : "r"((a)[0]), "r"((a)[1]), "r"((a)[2]), "r"((a)[3]),                  \
          "r"(b0), "r"(b1))

#define CP_ASYNC8(dst, src)                                                    \
    asm volatile("cp.async.ca.shared.global [%0], [%1], 8;"                    \
        :: "r"(dst), "l"(src))
#define CP_COMMIT() asm volatile("cp.async.commit_group;" ::: "memory")
#define CP_WAIT0()  asm volatile("cp.async.wait_group 0;" ::: "memory")

__device__ __forceinline__ uint32_t pack_bf16(float a, float b) {
    __nv_bfloat162 t = __floats2bfloat162_rn(a, b);
    return *reinterpret_cast<uint32_t*>(&t);
}

// split float4 into hi/lo bf16 packed words
__device__ __forceinline__ void split4(float4 v, uint32_t h[2], uint32_t l[2]) {
    __nv_bfloat16 hx = __float2bfloat16(v.x);
    __nv_bfloat16 hy = __float2bfloat16(v.y);
    __nv_bfloat16 hz = __float2bfloat16(v.z);
    __nv_bfloat16 hw = __float2bfloat16(v.w);
    float lx = v.x - __bfloat162float(hx);
    float ly = v.y - __bfloat162float(hy);
    float lz = v.z - __bfloat162float(hz);
    float lw = v.w - __bfloat162float(hw);
    __nv_bfloat162 h01; h01.x = hx; h01.y = hy;
    __nv_bfloat162 h23; h23.x = hz; h23.y = hw;
    h[0] = *reinterpret_cast<uint32_t*>(&h01);
    h[1] = *reinterpret_cast<uint32_t*>(&h23);
    l[0] = pack_bf16(lx, ly);
    l[1] = pack_bf16(lz, lw);
}

// ---------------- weight prologue: split + transpose ----------------
__global__ void split_w_kernel(const float* __restrict__ W, int layer) {
    int k = blockIdx.x;
    int n = threadIdx.x;
    float w = W[(size_t)k * COUT + n];
    __nv_bfloat16 h = __float2bfloat16(w);
    float l = w - __bfloat162float(h);
    g_Wth[layer][n][k] = h;
    g_Wtl[layer][n][k] = __float2bfloat16(l);
}

// ---------------- main fused layer ----------------
// MODE 0: support (K=512) -> g_h1 ; MODE 1: g_h1 -> g_h2 ;
// MODE 2: query + gather(g_h2) -> out
template <int MODE>
__global__ void __launch_bounds__(512)
layer_kernel(const float* __restrict__ Aext,
             const float* __restrict__ bias,
             const float* __restrict__ gamma,
             const float* __restrict__ beta,
             const int*   __restrict__ idx,
             float*       __restrict__ Oext)
{
    constexpr int K     = (MODE == 0) ? CIN : COUT;
    constexpr int NC    = K / KC;
    constexpr int LAYER = MODE;

    extern __shared__ __align__(16) char smc[];
    __shared__ int s_grow[TILE_M];

    const int tid  = threadIdx.x;
    const int wid  = tid >> 5;
    const int lane = tid & 31;
    const int rowBlk = blockIdx.x * TILE_M;

    const float* Asrc = (MODE == 1) ? g_h1 : Aext;
    float*       Odst = (MODE == 0) ? g_h1 : ((MODE == 1) ? g_h2 : Oext);

    const __nv_bfloat16* Wth = &g_Wth[LAYER][0][0];
    const __nv_bfloat16* Wtl = &g_Wtl[LAYER][0][0];

    const uint32_t sbase = smem_u32(smc);

    if (MODE == 2) {
        if (tid < TILE_M) {
            int grow = rowBlk + tid;
            s_grow[tid] = (grow >> 16) * Mm + idx[grow];
        }
        __syncthreads();
    }

    // ---- staging lambdas ----
    // A: 128 x 32 fp32 -> 1024 float4, 512 threads -> 2 each
    float4 vpipe[2];
    auto ldgA = [&](int kc) {
#pragma unroll
        for (int i = 0; i < 2; i++) {
            int s  = tid + i * 512;
            int r  = s >> 3;
            int c4 = (s & 7) * 4;
            if (MODE == 2) {
                float4 q = *(const float4*)(Aext + (size_t)(rowBlk + r) * COUT + kc + c4);
                float4 g = *(const float4*)(g_h2 + (size_t)s_grow[r] * COUT + kc + c4);
                vpipe[i] = make_float4(q.x + g.x, q.y + g.y, q.z + g.z, q.w + g.w);
            } else {
                vpipe[i] = *(const float4*)(Asrc + (size_t)(rowBlk + r) * K + kc + c4);
            }
        }
    };
    auto stsA = [&](int buf) {
        char* ab = smc + buf * BUF_BYTES;
#pragma unroll
        for (int i = 0; i < 2; i++) {
            int s  = tid + i * 512;
            int r  = s >> 3;
            int c4 = (s & 7) * 4;
            uint32_t h[2], l[2];
            split4(vpipe[i], h, l);
            int off = (r * ASTRE + c4) * 2;
            *(uint2*)(ab + off)           = make_uint2(h[0], h[1]);
            *(uint2*)(ab + A_BYTES + off) = make_uint2(l[0], l[1]);
        }
    };
    // B: 256 n-rows x 32 k bf16 per half, via cp.async 8B; 4 per half per thread
    auto cpB = [&](int kc, int buf) {
        uint32_t bh = sbase + buf * BUF_BYTES + 2 * A_BYTES;
        uint32_t bl = bh + B_BYTES;
#pragma unroll
        for (int i = 0; i < 4; i++) {
            int q   = tid + i * 512;          // 0..2047
            int n   = q >> 3;
            int seg = q & 7;
            uint32_t doff = (uint32_t)(n * ASTRE + seg * 4) * 2;
            size_t   soff = (size_t)n * CIN + kc + seg * 4;
            CP_ASYNC8(bh + doff, Wth + soff);
            CP_ASYNC8(bl + doff, Wtl + soff);
        }
    };

    // ---- accumulators ----
    const int wm = wid & 3;         // m group
    const int wn = wid >> 2;        // n group
    const int wr = wm * 32;
    const int wc = wn * 64;

    float acc[2][8][4];
#pragma unroll
    for (int mi = 0; mi < 2; mi++)
#pragma unroll
        for (int j = 0; j < 8; j++)
#pragma unroll
            for (int c = 0; c < 4; c++) acc[mi][j][c] = 0.f;

    // lane address components for ldmatrix
    const int a_r  = (lane & 15);
    const int a_kh = (lane >> 4) * 8;
    const int b_r  = ((lane >> 4) & 1) * 8 + (lane & 7);
    const int b_kh = ((lane >> 3) & 1) * 8;

    // ---- prime chunk 0 ----
    ldgA(0);
    cpB(0, 0);
    CP_COMMIT();
    stsA(0);

#pragma unroll 1
    for (int c = 0; c < NC; c++) {
        const int cb = c & 1;
        CP_WAIT0();
        __syncthreads();

        if (c + 1 < NC) {
            ldgA((c + 1) * KC);
            cpB((c + 1) * KC, (c + 1) & 1);
            CP_COMMIT();
        }

        // ---- MMAs on buffer cb ----
        const uint32_t aH = sbase + cb * BUF_BYTES;
        const uint32_t bH = aH + 2 * A_BYTES;
#pragma unroll
        for (int ks = 0; ks < 2; ks++) {
            const int k0 = ks * 16;
            uint32_t ah[2][4], al[2][4];
#pragma unroll
            for (int mi = 0; mi < 2; mi++) {
                uint32_t ad = aH + (uint32_t)((wr + mi * 16 + a_r) * ASTRE + k0 + a_kh) * 2;
                LDSM4(ah[mi], ad);
                LDSM4(al[mi], ad + A_BYTES);
            }
#pragma unroll
            for (int jp = 0; jp < 4; jp++) {
                uint32_t bhr[4], blr[4];
                uint32_t bd = bH + (uint32_t)((wc + jp * 16 + b_r) * ASTRE + k0 + b_kh) * 2;
                LDSM4(bhr, bd);
                LDSM4(blr, bd + B_BYTES);
#pragma unroll
                for (int mi = 0; mi < 2; mi++)
#pragma unroll
                    for (int jj = 0; jj < 2; jj++) {
                        float* C = acc[mi][jp * 2 + jj];
                        MMA_BF16(C, ah[mi], bhr[jj * 2], bhr[jj * 2 + 1]);
                        MMA_BF16(C, al[mi], bhr[jj * 2], bhr[jj * 2 + 1]);
                        MMA_BF16(C, ah[mi], blr[jj * 2], blr[jj * 2 + 1]);
                    }
            }
        }

        if (c + 1 < NC) stsA((c + 1) & 1);
    }

    // ---- fused epilogue: +bias, GroupNorm(8ch = one n8 tile), affine, lrelu
    const int qlane = lane & 3;
#pragma unroll
    for (int j = 0; j < 8; j++) {
        const int col = wc + j * 8 + 2 * qlane;
        const float2 bb = *reinterpret_cast<const float2*>(bias + col);
        const float2 gg = *reinterpret_cast<const float2*>(gamma + col);
        const float2 be = *reinterpret_cast<const float2*>(beta + col);
#pragma unroll
        for (int mi = 0; mi < 2; mi++) {
            float v0 = acc[mi][j][0] + bb.x;
            float v1 = acc[mi][j][1] + bb.y;
            float v2 = acc[mi][j][2] + bb.x;
            float v3 = acc[mi][j][3] + bb.y;

            float s0 = v0 + v1,           s1 = v2 + v3;
            float t0 = v0 * v0 + v1 * v1, t1 = v2 * v2 + v3 * v3;
            s0 += __shfl_xor_sync(0xffffffffu, s0, 1);
            s0 += __shfl_xor_sync(0xffffffffu, s0, 2);
            s1 += __shfl_xor_sync(0xffffffffu, s1, 1);
            s1 += __shfl_xor_sync(0xffffffffu, s1, 2);
            t0 += __shfl_xor_sync(0xffffffffu, t0, 1);
            t0 += __shfl_xor_sync(0xffffffffu, t0, 2);
            t1 += __shfl_xor_sync(0xffffffffu, t1, 1);
            t1 += __shfl_xor_sync(0xffffffffu, t1, 2);

            const float m0 = s0 * 0.125f, m1 = s1 * 0.125f;
            const float r0 = rsqrtf(fmaxf(t0 * 0.125f - m0 * m0, 0.f) + EPSv);
            const float r1 = rsqrtf(fmaxf(t1 * 0.125f - m1 * m1, 0.f) + EPSv);

            float y0 = (v0 - m0) * r0 * gg.x + be.x;
            float y1 = (v1 - m0) * r0 * gg.y + be.y;
            float y2 = (v2 - m1) * r1 * gg.x + be.x;
            float y3 = (v3 - m1) * r1 * gg.y + be.y;
            y0 = (y0 >= 0.f) ? y0 : SLOPEv * y0;
            y1 = (y1 >= 0.f) ? y1 : SLOPEv * y1;
            y2 = (y2 >= 0.f) ? y2 : SLOPEv * y2;
            y3 = (y3 >= 0.f) ? y3 : SLOPEv * y3;

            const size_t row = (size_t)rowBlk + wr + mi * 16 + (lane >> 2);
            *reinterpret_cast<float2*>(Odst + row * COUT + col) =
                make_float2(y0, y1);
            *reinterpret_cast<float2*>(Odst + (row + 8) * COUT + col) =
                make_float2(y2, y3);
        }
    }
}

extern "C" void kernel_launch(void* const* d_in, const int* in_sizes, int n_in,
                              void* d_out, int out_size)
{
    (void)in_sizes; (void)n_in; (void)out_size;
    const float* query   = (const float*)d_in[0];
    const float* support = (const float*)d_in[1];
    const int*   idx     = (const int*)d_in[2];
    const float* W1  = (const float*)d_in[3];
    const float* b1  = (const float*)d_in[4];
    const float* g1  = (const float*)d_in[5];
    const float* be1 = (const float*)d_in[6];
    const float* W2  = (const float*)d_in[7];
    const float* b2  = (const float*)d_in[8];
    const float* g2  = (const float*)d_in[9];
    const float* be2 = (const float*)d_in[10];
    const float* W3  = (const float*)d_in[11];
    const float* b3  = (const float*)d_in[12];
    const float* g3  = (const float*)d_in[13];
    const float* be3 = (const float*)d_in[14];
    float* out = (float*)d_out;

    split_w_kernel<<<CIN,  COUT>>>(W1, 0);
    split_w_kernel<<<COUT, COUT>>>(W2, 1);
    split_w_kernel<<<COUT, COUT>>>(W3, 2);

    cudaFuncSetAttribute(layer_kernel<0>,
        cudaFuncAttributeMaxDynamicSharedMemorySize, (int)SMEM_DYN);
    cudaFuncSetAttribute(layer_kernel<1>,
        cudaFuncAttributeMaxDynamicSharedMemorySize, (int)SMEM_DYN);
    cudaFuncSetAttribute(layer_kernel<2>,
        cudaFuncAttributeMaxDynamicSharedMemorySize, (int)SMEM_DYN);

    layer_kernel<0><<<ROWS12 / TILE_M, 512, SMEM_DYN>>>(
        support, b1, g1, be1, nullptr, nullptr);
    layer_kernel<1><<<ROWS12 / TILE_M, 512, SMEM_DYN>>>(
        nullptr, b2, g2, be2, nullptr, nullptr);
    layer_kernel<2><<<ROWS3 / TILE_M, 512, SMEM_DYN>>>(
        query, b3, g3, be3, idx, out);
}